// round 7
// baseline (speedup 1.0000x reference)
#include <cuda_runtime.h>
#include <cuda_bf16.h>
#include <math.h>

// Problem constants (from reference): B=16, L=2048, D=4096, TOTAL=B*L
#define D_DIM     4096
#define D4        (D_DIM / 4)          // 1024 float4 per row
#define NSPLIT    16                   // splits along sequence dim
#define BLK       256                  // threads per block
#define NCHUNK    (D4 / BLK)           // 4 column chunks of float4
#define B_MAX     64

// Scratch (fully overwritten each call; no zeroing dependencies):
__device__ float g_partial[B_MAX * NSPLIT * D_DIM];   // [B][NSPLIT][D]
__device__ float g_mean[B_MAX * D_DIM];               // [B][D]
__device__ float g_sq[B_MAX * NCHUNK];                // [B][NCHUNK] partial sum-of-squares

// ---------------------------------------------------------------------------
// Kernel 1: per-(segment, split, column-chunk) masked partial sums.
// grid = (NCHUNK, NSPLIT, B) = 1024 CTAs, block = BLK. HBM-bound streaming.
// ---------------------------------------------------------------------------
__global__ __launch_bounds__(BLK)
void pool_partial(const float* __restrict__ hs,
                  const int* __restrict__ plens,
                  const int* __restrict__ ilens)
{
    const int chunk = blockIdx.x;
    const int split = blockIdx.y;
    const int b     = blockIdx.z;
    const int t     = threadIdx.x;

    // segment start = exclusive cumsum of prompt_lens (B tiny; L2-resident)
    int start = 0;
    #pragma unroll 1
    for (int i = 0; i < b; ++i) start += plens[i];
    const int plen = plens[b];
    const int il   = ilens[b];

    const int rps = (plen + NSPLIT - 1) / NSPLIT;
    int r0 = split * rps;
    int r1 = r0 + rps; if (r1 > plen) r1 = plen;
    if (r0 < il) r0 = il;

    const int col = chunk * BLK + t;             // float4 column index
    const float4* __restrict__ hs4 = (const float4*)hs;

    float4 a0 = make_float4(0.f, 0.f, 0.f, 0.f);
    float4 a1 = make_float4(0.f, 0.f, 0.f, 0.f);

    int r = r0;
    for (; r + 8 <= r1; r += 8) {
        size_t base = (size_t)(start + r) * D4 + col;
        float4 v0 = hs4[base];
        float4 v1 = hs4[base + 1 * (size_t)D4];
        float4 v2 = hs4[base + 2 * (size_t)D4];
        float4 v3 = hs4[base + 3 * (size_t)D4];
        float4 v4 = hs4[base + 4 * (size_t)D4];
        float4 v5 = hs4[base + 5 * (size_t)D4];
        float4 v6 = hs4[base + 6 * (size_t)D4];
        float4 v7 = hs4[base + 7 * (size_t)D4];
        a0.x += v0.x + v1.x + v2.x + v3.x;
        a0.y += v0.y + v1.y + v2.y + v3.y;
        a0.z += v0.z + v1.z + v2.z + v3.z;
        a0.w += v0.w + v1.w + v2.w + v3.w;
        a1.x += v4.x + v5.x + v6.x + v7.x;
        a1.y += v4.y + v5.y + v6.y + v7.y;
        a1.z += v4.z + v5.z + v6.z + v7.z;
        a1.w += v4.w + v5.w + v6.w + v7.w;
    }
    for (; r < r1; ++r) {
        float4 v = hs4[(size_t)(start + r) * D4 + col];
        a0.x += v.x; a0.y += v.y; a0.z += v.z; a0.w += v.w;
    }
    a0.x += a1.x; a0.y += a1.y; a0.z += a1.z; a0.w += a1.w;

    float4* __restrict__ part = (float4*)g_partial;
    part[((size_t)b * NSPLIT + split) * D4 + col] = a0;
}

// ---------------------------------------------------------------------------
// Kernel 2: reduce NSPLIT partials -> mean; per-(b,chunk) sum of squares.
// grid = (NCHUNK, B) = 64 CTAs, block = BLK. Each thread owns ONE float4 col.
// Two interleaved 8-deep chains: 8+ independent L2 loads in flight, low regs.
// ---------------------------------------------------------------------------
__global__ __launch_bounds__(BLK)
void reduce_mean(const int* __restrict__ plens,
                 const int* __restrict__ ilens)
{
    const int chunk = blockIdx.x;
    const int b     = blockIdx.y;
    const int t     = threadIdx.x;
    const int col   = chunk * BLK + t;

    const float inv = 1.0f / (float)(plens[b] - ilens[b]);

    const float4* __restrict__ part = (const float4*)g_partial;
    const size_t base = (size_t)b * NSPLIT * D4 + col;

    float4 s0 = make_float4(0.f, 0.f, 0.f, 0.f);
    float4 s1 = make_float4(0.f, 0.f, 0.f, 0.f);
    #pragma unroll
    for (int sp = 0; sp < NSPLIT; sp += 2) {
        float4 va = part[base + (size_t)sp * D4];
        float4 vb = part[base + (size_t)(sp + 1) * D4];
        s0.x += va.x; s0.y += va.y; s0.z += va.z; s0.w += va.w;
        s1.x += vb.x; s1.y += vb.y; s1.z += vb.z; s1.w += vb.w;
    }
    float4 s = make_float4((s0.x + s1.x) * inv, (s0.y + s1.y) * inv,
                           (s0.z + s1.z) * inv, (s0.w + s1.w) * inv);

    ((float4*)g_mean)[(size_t)b * D4 + col] = s;

    // sum of squares: warp shuffle reduce, then smem across 8 warps
    float sq = s.x * s.x + s.y * s.y + s.z * s.z + s.w * s.w;
    #pragma unroll
    for (int off = 16; off > 0; off >>= 1)
        sq += __shfl_xor_sync(0xFFFFFFFFu, sq, off);

    __shared__ float wsum[BLK / 32];
    if ((t & 31) == 0) wsum[t >> 5] = sq;
    __syncthreads();
    if (t == 0) {
        float tot = 0.f;
        #pragma unroll
        for (int w = 0; w < BLK / 32; ++w) tot += wsum[w];
        g_sq[b * NCHUNK + chunk] = tot;
    }
}

// ---------------------------------------------------------------------------
// Kernel 3: L2-normalize mean and write output.
// grid = (NCHUNK, B), block = BLK. Each block redundantly sums NCHUNK scalars.
// ---------------------------------------------------------------------------
__global__ __launch_bounds__(BLK)
void normalize_out(float* __restrict__ out)
{
    const int chunk = blockIdx.x;
    const int b     = blockIdx.y;
    const int t     = threadIdx.x;
    const int col   = chunk * BLK + t;

    float tot = 0.f;
    #pragma unroll
    for (int c = 0; c < NCHUNK; ++c) tot += g_sq[b * NCHUNK + c];

    const float rn = 1.0f / fmaxf(sqrtf(tot), 1e-12f);

    float4 m = ((const float4*)g_mean)[(size_t)b * D4 + col];
    m.x *= rn; m.y *= rn; m.z *= rn; m.w *= rn;
    ((float4*)out)[(size_t)b * D4 + col] = m;
}

extern "C" void kernel_launch(void* const* d_in, const int* in_sizes, int n_in,
                              void* d_out, int out_size)
{
    const float* hs    = (const float*)d_in[0];
    const int*   plens = (const int*)d_in[1];
    const int*   ilens = (const int*)d_in[2];
    float*       out   = (float*)d_out;

    const int B = in_sizes[1];   // number of sequences

    dim3 grid1(NCHUNK, NSPLIT, B);
    pool_partial<<<grid1, BLK>>>(hs, plens, ilens);

    dim3 grid2(NCHUNK, B);
    reduce_mean<<<grid2, BLK>>>(plens, ilens);

    normalize_out<<<grid2, BLK>>>(out);
}

// round 9
// speedup vs baseline: 1.0605x; 1.0605x over previous
#include <cuda_runtime.h>
#include <cuda_bf16.h>
#include <math.h>

// Problem constants (from reference): B=16, L=2048, D=4096, TOTAL=B*L
#define D_DIM     4096
#define D4        (D_DIM / 4)          // 1024 float4 per row
#define NSPLIT    16                   // splits along sequence dim
#define BLK       256                  // threads per block
#define NCHUNK    (D4 / BLK)           // 4 column chunks of float4
#define B_MAX     64

// Scratch (fully overwritten each call; no zeroing dependencies):
__device__ float g_partial[B_MAX * NSPLIT * D_DIM];   // [B][NSPLIT][D]
__device__ float g_mean[B_MAX * D_DIM];               // [B][D]
__device__ float g_sq[B_MAX * NCHUNK];                // [B][NCHUNK] partial sum-of-squares

// ---------------------------------------------------------------------------
// Kernel 1: per-(segment, split, column-chunk) masked partial sums.
// grid = (NCHUNK, NSPLIT, B) = 1024 CTAs, block = BLK. HBM-bound streaming.
// Unroll-4 (MLP_p1=4): deeper unrolls measurably regress via cross-CTA
// L1tex-queue spread (R7: unroll-8 cost 12 us on this kernel).
// ---------------------------------------------------------------------------
__global__ __launch_bounds__(BLK)
void pool_partial(const float* __restrict__ hs,
                  const int* __restrict__ plens,
                  const int* __restrict__ ilens)
{
    const int chunk = blockIdx.x;   // column chunk
    const int split = blockIdx.y;   // sequence split
    const int b     = blockIdx.z;   // segment id
    const int t     = threadIdx.x;

    // segment start = exclusive cumsum of prompt_lens (B tiny; L2-resident)
    int start = 0;
    #pragma unroll 1
    for (int i = 0; i < b; ++i) start += plens[i];
    const int plen = plens[b];
    const int il   = ilens[b];

    // row range for this split, clipped below by instruction_len
    const int rps = (plen + NSPLIT - 1) / NSPLIT;
    int r0 = split * rps;
    int r1 = r0 + rps; if (r1 > plen) r1 = plen;
    if (r0 < il) r0 = il;

    const int col = chunk * BLK + t;             // float4 column index
    const float4* __restrict__ hs4 = (const float4*)hs;

    float4 acc = make_float4(0.f, 0.f, 0.f, 0.f);

    int r = r0;
    // unrolled by 4 for memory-level parallelism (sweet spot per R7 data)
    for (; r + 4 <= r1; r += 4) {
        size_t base = (size_t)(start + r) * D4 + col;
        float4 v0 = hs4[base];
        float4 v1 = hs4[base + D4];
        float4 v2 = hs4[base + 2 * (size_t)D4];
        float4 v3 = hs4[base + 3 * (size_t)D4];
        acc.x += v0.x + v1.x + v2.x + v3.x;
        acc.y += v0.y + v1.y + v2.y + v3.y;
        acc.z += v0.z + v1.z + v2.z + v3.z;
        acc.w += v0.w + v1.w + v2.w + v3.w;
    }
    for (; r < r1; ++r) {
        float4 v = hs4[(size_t)(start + r) * D4 + col];
        acc.x += v.x; acc.y += v.y; acc.z += v.z; acc.w += v.w;
    }

    float4* __restrict__ part = (float4*)g_partial;
    part[((size_t)b * NSPLIT + split) * D4 + col] = acc;
}

// ---------------------------------------------------------------------------
// Kernel 2: reduce NSPLIT partials -> mean; per-(b,chunk) sum of squares.
// grid = (NCHUNK, B) = 64 CTAs, block = BLK. Each thread owns ONE float4 col.
// Two interleaved chains: 8+ independent L2 loads in flight, low regs.
// ---------------------------------------------------------------------------
__global__ __launch_bounds__(BLK)
void reduce_mean(const int* __restrict__ plens,
                 const int* __restrict__ ilens)
{
    const int chunk = blockIdx.x;
    const int b     = blockIdx.y;
    const int t     = threadIdx.x;
    const int col   = chunk * BLK + t;

    const float inv = 1.0f / (float)(plens[b] - ilens[b]);

    const float4* __restrict__ part = (const float4*)g_partial;
    const size_t base = (size_t)b * NSPLIT * D4 + col;

    float4 s0 = make_float4(0.f, 0.f, 0.f, 0.f);
    float4 s1 = make_float4(0.f, 0.f, 0.f, 0.f);
    #pragma unroll
    for (int sp = 0; sp < NSPLIT; sp += 2) {
        float4 va = part[base + (size_t)sp * D4];
        float4 vb = part[base + (size_t)(sp + 1) * D4];
        s0.x += va.x; s0.y += va.y; s0.z += va.z; s0.w += va.w;
        s1.x += vb.x; s1.y += vb.y; s1.z += vb.z; s1.w += vb.w;
    }
    float4 s = make_float4((s0.x + s1.x) * inv, (s0.y + s1.y) * inv,
                           (s0.z + s1.z) * inv, (s0.w + s1.w) * inv);

    ((float4*)g_mean)[(size_t)b * D4 + col] = s;

    // sum of squares: warp shuffle reduce, then smem across 8 warps
    float sq = s.x * s.x + s.y * s.y + s.z * s.z + s.w * s.w;
    #pragma unroll
    for (int off = 16; off > 0; off >>= 1)
        sq += __shfl_xor_sync(0xFFFFFFFFu, sq, off);

    __shared__ float wsum[BLK / 32];
    if ((t & 31) == 0) wsum[t >> 5] = sq;
    __syncthreads();
    if (t == 0) {
        float tot = 0.f;
        #pragma unroll
        for (int w = 0; w < BLK / 32; ++w) tot += wsum[w];
        g_sq[b * NCHUNK + chunk] = tot;
    }
}

// ---------------------------------------------------------------------------
// Kernel 3: L2-normalize mean and write output.
// grid = (NCHUNK, B), block = BLK. Each block redundantly sums NCHUNK scalars.
// ---------------------------------------------------------------------------
__global__ __launch_bounds__(BLK)
void normalize_out(float* __restrict__ out)
{
    const int chunk = blockIdx.x;
    const int b     = blockIdx.y;
    const int t     = threadIdx.x;
    const int col   = chunk * BLK + t;

    float tot = 0.f;
    #pragma unroll
    for (int c = 0; c < NCHUNK; ++c) tot += g_sq[b * NCHUNK + c];

    const float rn = 1.0f / fmaxf(sqrtf(tot), 1e-12f);

    float4 m = ((const float4*)g_mean)[(size_t)b * D4 + col];
    m.x *= rn; m.y *= rn; m.z *= rn; m.w *= rn;
    ((float4*)out)[(size_t)b * D4 + col] = m;
}

extern "C" void kernel_launch(void* const* d_in, const int* in_sizes, int n_in,
                              void* d_out, int out_size)
{
    const float* hs    = (const float*)d_in[0];
    const int*   plens = (const int*)d_in[1];
    const int*   ilens = (const int*)d_in[2];
    float*       out   = (float*)d_out;

    const int B = in_sizes[1];   // number of sequences

    dim3 grid1(NCHUNK, NSPLIT, B);
    pool_partial<<<grid1, BLK>>>(hs, plens, ilens);

    dim3 grid2(NCHUNK, B);
    reduce_mean<<<grid2, BLK>>>(plens, ilens);

    normalize_out<<<grid2, BLK>>>(out);
}